// round 14
// baseline (speedup 1.0000x reference)
#include <cuda_runtime.h>
#include <cstdint>

#define BATCH 16
#define LQ    16384
#define NC    21
#define HID   256
#define HH    128
#define WW    128
#define SEGG  128
#define NSEG  128

#define T0SPLIT   2048
#define P1BPB     (T0SPLIT / 256)            // 8 blocks per batch
#define P2BPB     ((LQ - T0SPLIT) / 256)     // 56 blocks per batch
#define P2BLOCKS  (BATCH * P2BPB)            // 896

typedef unsigned long long u64;

// ---------------- constant memory for small params ----------------
__constant__ float c_w2  [NC * HID];
__constant__ float c_tr  [NC * NC];
__constant__ float c_b1  [HID];
__constant__ float c_b2  [NC];
__constant__ float c_st  [NC];
__constant__ float c_en  [NC];

// ---------------- device scratch ----------------
__device__ float         g_emis  [BATCH * LQ * 32];   // row layout (bp)
__device__ float         g_emisT [BATCH * NC * LQ];   // transposed (fwd)
__device__ float         g_scores[BATCH * LQ * 32];
__device__ unsigned char g_bp    [BATCH * LQ * 32];
__device__ unsigned char g_segmap[BATCH * NSEG * 32];
__device__ unsigned char g_segend[BATCH * NSEG];
__device__ int           g_lasttag[BATCH];
__device__ int           g_p2done;
__device__ int           g_progress[BATCH];           // fwd score progress

// ---------------- f32x2 helpers ----------------
__device__ __forceinline__ u64 pk2(float lo, float hi)
{ u64 r; asm("mov.b64 %0,{%1,%2};" : "=l"(r) : "f"(lo), "f"(hi)); return r; }
__device__ __forceinline__ void upk2(u64 v, float& lo, float& hi)
{ asm("mov.b64 {%0,%1},%2;" : "=f"(lo), "=f"(hi) : "l"(v)); }
__device__ __forceinline__ u64 fma2(u64 a, u64 b, u64 c)
{ u64 d; asm("fma.rn.f32x2 %0,%1,%2,%3;" : "=l"(d) : "l"(a), "l"(b), "l"(c)); return d; }

// ---------------- ordered smem ops (warp-lockstep comms) ----------------
__device__ __forceinline__ uint32_t smem_u32(const void* p)
{ uint32_t a; asm("{ .reg .u64 t; cvta.to.shared.u64 t, %1; cvt.u32.u64 %0, t; }"
                  : "=r"(a) : "l"(p)); return a; }
__device__ __forceinline__ void sts32(uint32_t addr, float v)
{ asm volatile("st.shared.b32 [%0], %1;" :: "r"(addr), "f"(v)); }
__device__ __forceinline__ float4 lds128(uint32_t addr)
{ float4 r; asm volatile("ld.shared.v4.f32 {%0,%1,%2,%3}, [%4];"
      : "=f"(r.x), "=f"(r.y), "=f"(r.z), "=f"(r.w) : "r"(addr)); return r; }
__device__ __forceinline__ float lds32(uint32_t addr)
{ float r; asm volatile("ld.shared.f32 %0, [%1];" : "=f"(r) : "r"(addr)); return r; }

// =====================================================================
// Kernel 1: fused conv backbone; writes BOTH emission layouts.
// conv1 packed over h-pairs (bit-identical to scalar).
// =====================================================================
__global__ __launch_bounds__(256) void emis_kernel(
    const float* __restrict__ x,
    const float* __restrict__ w1,
    int t0, int bpb)
{
    __shared__ u64 w1p[128 * 28];
    const int tid = threadIdx.x;

    if (t0 == 0 && blockIdx.x == 0 && tid == 0) {
        g_p2done = 0;
        for (int b = 0; b < BATCH; b++) g_progress[b] = 0;
    }

    for (int i = tid; i < 128 * 27; i += 256) {
        int h2 = i / 27, k = i - h2 * 27;
        w1p[h2 * 28 + k] = pk2(w1[(2 * h2) * 27 + k], w1[(2 * h2 + 1) * 27 + k]);
    }
    __syncthreads();

    const int b = blockIdx.x / bpb;
    const int t = t0 + (blockIdx.x % bpb) * 256 + tid;
    const int y  = t >> 7;
    const int xx = t & 127;

    float patch[27];
#pragma unroll
    for (int ci = 0; ci < 3; ci++)
#pragma unroll
        for (int dy = 0; dy < 3; dy++)
#pragma unroll
            for (int dx = 0; dx < 3; dx++) {
                int yy = y + dy - 1;
                int xi = xx + dx - 1;
                bool ok = (yy >= 0) & (yy < HH) & (xi >= 0) & (xi < WW);
                patch[ci * 9 + dy * 3 + dx] =
                    ok ? x[((b * 3 + ci) * HH + yy) * WW + xi] : 0.0f;
            }

    u64 pp[27];
#pragma unroll
    for (int k = 0; k < 27; k++) pp[k] = pk2(patch[k], patch[k]);

    float emit[NC];
#pragma unroll
    for (int c = 0; c < NC; c++) emit[c] = 0.0f;

#pragma unroll 2
    for (int h2 = 0; h2 < 128; h2++) {
        u64 a2 = 0;
#pragma unroll
        for (int k = 0; k < 27; k++)
            a2 = fma2(w1p[h2 * 28 + k], pp[k], a2);

        float aE, aO;
        upk2(a2, aE, aO);
        aE = fmaxf(aE + c_b1[2 * h2],     0.0f);
        aO = fmaxf(aO + c_b1[2 * h2 + 1], 0.0f);

#pragma unroll
        for (int c = 0; c < NC; c++)
            emit[c] = __fmaf_rn(c_w2[c * HID + 2 * h2], aE, emit[c]);
#pragma unroll
        for (int c = 0; c < NC; c++)
            emit[c] = __fmaf_rn(c_w2[c * HID + 2 * h2 + 1], aO, emit[c]);
    }

    const int base = (b * LQ + t) * 32;
#pragma unroll
    for (int c = 0; c < NC; c++) {
        float v = emit[c] + c_b2[c];
        g_emis[base + c] = v;
        g_emisT[(b * NC + c) * LQ + t] = v;
    }

    if (t0 > 0) {
        __syncthreads();
        if (tid == 0) { __threadfence(); atomicAdd(&g_p2done, 1); }
    }
}

// =====================================================================
// Kernel 2: Viterbi forward, 1 warp per batch, lockstep smem broadcast.
// Emission reloads from transposed layout: 2x LDG.128 per 8 steps.
// Publishes per-batch progress every 16 chunks for bp overlap.
// =====================================================================
__device__ __forceinline__ float step_math(
    float4 a, float4 b4, float4 c4, float4 d4, float4 f4, float g,
    float e, const float* Tc)
{
    float v[NC];
    v[0]  = __fmaf_rn(a.x,  1.0f, Tc[0]);
    v[1]  = __fmaf_rn(a.y,  1.0f, Tc[1]);
    v[2]  = __fmaf_rn(a.z,  1.0f, Tc[2]);
    v[3]  = __fmaf_rn(a.w,  1.0f, Tc[3]);
    v[4]  = __fmaf_rn(b4.x, 1.0f, Tc[4]);
    v[5]  = __fmaf_rn(b4.y, 1.0f, Tc[5]);
    v[6]  = __fmaf_rn(b4.z, 1.0f, Tc[6]);
    v[7]  = __fmaf_rn(b4.w, 1.0f, Tc[7]);
    v[8]  = __fmaf_rn(c4.x, 1.0f, Tc[8]);
    v[9]  = __fmaf_rn(c4.y, 1.0f, Tc[9]);
    v[10] = __fmaf_rn(c4.z, 1.0f, Tc[10]);
    v[11] = __fmaf_rn(c4.w, 1.0f, Tc[11]);
    v[12] = __fmaf_rn(d4.x, 1.0f, Tc[12]);
    v[13] = __fmaf_rn(d4.y, 1.0f, Tc[13]);
    v[14] = __fmaf_rn(d4.z, 1.0f, Tc[14]);
    v[15] = __fmaf_rn(d4.w, 1.0f, Tc[15]);
    v[16] = __fmaf_rn(f4.x, 1.0f, Tc[16]);
    v[17] = __fmaf_rn(f4.y, 1.0f, Tc[17]);
    v[18] = __fmaf_rn(f4.z, 1.0f, Tc[18]);
    v[19] = __fmaf_rn(f4.w, 1.0f, Tc[19]);
    v[20] = __fmaf_rn(g,    1.0f, Tc[20]);

#pragma unroll
    for (int st = 1; st < NC; st <<= 1)
#pragma unroll
        for (int i = 0; i + st < NC; i += 2 * st)
            v[i] = fmaxf(v[i], v[i + st]);

    return __fmaf_rn(v[0], 1.0f, e);
}

#define FWD_STEP(RBASE, WLANE, EJ, SOFF)                                 \
    {                                                                    \
        float4 A = lds128(RBASE);                                        \
        float4 B = lds128((RBASE) + 16);                                 \
        float4 C = lds128((RBASE) + 32);                                 \
        float4 D = lds128((RBASE) + 48);                                 \
        float4 F = lds128((RBASE) + 64);                                 \
        float  G = lds32((RBASE) + 80);                                  \
        s = step_math(A, B, C, D, F, G, EJ, Tc);                         \
        sts32(WLANE, s);                                                 \
        Sp[SOFF] = s;                                                    \
    }

#define CHUNK8()                                                         \
    __syncwarp();                                                        \
    FWD_STEP(a1, a0w, ep[0], 0 * 32)                                     \
    FWD_STEP(a0, a1w, ep[1], 1 * 32)                                     \
    FWD_STEP(a1, a0w, ep[2], 2 * 32)                                     \
    FWD_STEP(a0, a1w, ep[3], 3 * 32)                                     \
    FWD_STEP(a1, a0w, ep[4], 4 * 32)                                     \
    FWD_STEP(a0, a1w, ep[5], 5 * 32)                                     \
    FWD_STEP(a1, a0w, ep[6], 6 * 32)                                     \
    FWD_STEP(a0, a1w, ep[7], 7 * 32)

#define RELOAD8()                                                        \
    {                                                                    \
        float4 u0 = __ldg((const float4*)EpT);                           \
        float4 u1 = __ldg((const float4*)(EpT + 4));                     \
        ep[0] = u0.x; ep[1] = u0.y; ep[2] = u0.z; ep[3] = u0.w;          \
        ep[4] = u1.x; ep[5] = u1.y; ep[6] = u1.z; ep[7] = u1.w;          \
        EpT += 8;                                                        \
    }

// chunk counts: steps 8..16383 = 2047 chunks of 8.
//   loop1 = T0SPLIT/8 - 2 = 254   (t: 8 .. 2039; reloads stay < 2048)
//   loop2 = (LQ - T0SPLIT)/8 = 1792  (t: 2040 .. 16375)
//   tail  = 1 chunk, no reload       (t: 16376 .. 16383)
//   check: 254 + 1792 + 1 = 2047  OK
#define L1CHUNKS (T0SPLIT / 8 - 2)
#define L2CHUNKS ((LQ - T0SPLIT) / 8)

__global__ __launch_bounds__(32) void fwd_kernel()
{
    const int b    = blockIdx.x;
    const int lane = threadIdx.x;
    const int nn   = lane < NC ? lane : NC - 1;

    const float* ET = g_emisT  + (b * NC + nn) * LQ;   // lane's emission row
    float*       S  = g_scores + b * LQ * 32;

    __shared__ __align__(16) float sb0[32];
    __shared__ __align__(16) float sb1[32];

    const uint32_t a0  = smem_u32(sb0);
    const uint32_t a1  = smem_u32(sb1);
    const uint32_t a0w = a0 + lane * 4;
    const uint32_t a1w = a1 + lane * 4;

    float Tc[NC];
#pragma unroll
    for (int p = 0; p < NC; p++) Tc[p] = c_tr[p * NC + nn];

    // t = 0 -> sb0 (invariant: after step t, s lives in sb[t&1])
    float s = __fmaf_rn(ET[0], 1.0f, c_st[nn]);
    S[lane] = s;
    sts32(a0w, s);

    // peel t = 1..7
#pragma unroll
    for (int t = 1; t < 8; t++) {
        float e = __ldg(&ET[t]);
        uint32_t rb = (t & 1) ? a0 : a1;
        uint32_t wb = (t & 1) ? a1w : a0w;
        __syncwarp();
        float4 A = lds128(rb);
        float4 B = lds128(rb + 16);
        float4 C = lds128(rb + 32);
        float4 D = lds128(rb + 48);
        float4 F = lds128(rb + 64);
        float  G = lds32(rb + 80);
        s = step_math(A, B, C, D, F, G, e, Tc);
        sts32(wb, s);
        S[t * 32 + lane] = s;
    }

    // prefetch t = 8..15 (vector loads from transposed layout)
    float ep[8];
    {
        float4 u0 = __ldg((const float4*)(ET + 8));
        float4 u1 = __ldg((const float4*)(ET + 12));
        ep[0] = u0.x; ep[1] = u0.y; ep[2] = u0.z; ep[3] = u0.w;
        ep[4] = u1.x; ep[5] = u1.y; ep[6] = u1.z; ep[7] = u1.w;
    }

    float*       Sp  = S + 8 * 32 + lane;
    const float* EpT = ET + 16;
    int tdone = 8;                       // scores written for t < tdone

    // loop 1: t = 8 .. 2039
#pragma unroll 1
    for (int c = 0; c < L1CHUNKS; c++) {
        CHUNK8()
        RELOAD8()
        Sp += 256;
        tdone += 8;
        if ((c & 15) == 15) {            // uniform, every 128 steps
            __threadfence();
            *(volatile int*)&g_progress[b] = tdone;
        }
    }

    // wait for emis part 2 (t >= T0SPLIT)
    while (*(volatile int*)&g_p2done < P2BLOCKS) { }
    __threadfence();

    // loop 2: t = 2040 .. 16375
#pragma unroll 1
    for (int c = 0; c < L2CHUNKS; c++) {
        CHUNK8()
        RELOAD8()
        Sp += 256;
        tdone += 8;
        if ((c & 15) == 15) {
            __threadfence();
            *(volatile int*)&g_progress[b] = tdone;
        }
    }

    // final chunk t = 16376..16383, no reload
    CHUNK8()

    // final tag: first-max over lanes 0..20
    float vend = s + c_en[nn];
    __shared__ float vs[32];
    vs[lane] = vend;
    __syncwarp();
    if (lane == 0) {
        float best = vs[0];
        int   bi   = 0;
#pragma unroll
        for (int p = 1; p < NC; p++)
            if (vs[p] > best) { best = vs[p]; bi = p; }
        g_lasttag[b] = bi;
    }
    __syncwarp();
    __threadfence();                      // all scores + lasttag visible
    *(volatile int*)&g_progress[b] = LQ;  // uniform store, same value
}

// =====================================================================
// Kernel 3: backpointers — gated per 256-t tile on fwd progress, so it
// overlaps the fwd kernel. Math unchanged (bit-matches jnp.argmax).
// =====================================================================
__global__ __launch_bounds__(256) void bp_kernel()
{
    const int b  = blockIdx.x >> 6;
    const int tb = (blockIdx.x & 63) << 8;

    if (threadIdx.x == 0) {
        while (*(volatile int*)&g_progress[b] < tb + 256) { }
    }
    __syncthreads();
    __threadfence();

    const int t = tb + threadIdx.x;
    if (t == 0) return;

    const float* Sp = g_scores + (b * LQ + (t - 1)) * 32;
    const float* Ee = g_emis   + (b * LQ + t) * 32;
    unsigned char* bp = g_bp   + (b * LQ + t) * 32;

    float sv[NC], ev[NC];
#pragma unroll
    for (int p = 0; p < NC; p++) sv[p] = Sp[p];
#pragma unroll
    for (int c = 0; c < NC; c++) ev[c] = Ee[c];

#pragma unroll 3
    for (int n = 0; n < NC; n++) {
        float best = -3.0e38f;
        int bi = 0;
        float e = ev[n];
#pragma unroll
        for (int p = 0; p < NC; p++) {
            float a = __fmaf_rn(sv[p], 1.0f, c_tr[p * NC + n]);
            float v = __fmaf_rn(a,     1.0f, e);
            if (v > best) { best = v; bi = p; }
        }
        bp[n] = (unsigned char)bi;
    }
}

// =====================================================================
// Kernel 4a: per-segment end->start tag maps
// =====================================================================
__global__ __launch_bounds__(32) void segmap_kernel()
{
    const int b    = blockIdx.x >> 7;
    const int sg   = blockIdx.x & (NSEG - 1);
    const int lo   = sg * SEGG;
    const int lane = threadIdx.x;

    __shared__ unsigned char bps[SEGG][32];
    const unsigned* src = (const unsigned*)(g_bp + (b * LQ + lo) * 32);
    unsigned* dst = (unsigned*)bps;
    for (int i = lane; i < SEGG * 8; i += 32) dst[i] = src[i];
    __syncwarp();

    int tag = lane < NC ? lane : NC - 1;
    for (int r = SEGG - 1; r >= 1; r--) tag = bps[r][tag & 31];
    g_segmap[(b * NSEG + sg) * 32 + lane] = (unsigned char)tag;
}

// =====================================================================
// Kernel 4b: compose maps -> tag at end of every segment
// =====================================================================
__global__ __launch_bounds__(32) void compose_kernel()
{
    const int b    = blockIdx.x;
    const int lane = threadIdx.x;

    __shared__ unsigned char maps[NSEG][32];
    __shared__ unsigned char bnd [NSEG][32];
    __shared__ unsigned char se  [NSEG];

    {
        const unsigned* src = (const unsigned*)(g_segmap + b * NSEG * 32);
        unsigned* dst = (unsigned*)maps;
        for (int i = lane; i < NSEG * 8; i += 32) dst[i] = src[i];
        unsigned* dstb = (unsigned*)bnd;
        const unsigned* gb = (const unsigned*)g_bp;
        for (int i = lane; i < NSEG * 8; i += 32) {
            int s2 = i >> 3, w = i & 7;
            dstb[i] = gb[(size_t)(b * LQ + s2 * SEGG) * 8 + w];
        }
    }
    __syncwarp();

    if (lane == 0) {
        int tag = g_lasttag[b] & 31;
        for (int s2 = NSEG - 1; s2 >= 0; s2--) {
            se[s2] = (unsigned char)tag;
            int tstart = maps[s2][tag] & 31;
            if (s2 > 0) tag = bnd[s2][tstart] & 31;
        }
    }
    __syncwarp();
    for (int i = lane; i < NSEG; i += 32) g_segend[b * NSEG + i] = se[i];
}

// =====================================================================
// Kernel 4c: re-chase each segment, emit tags as FLOAT
// =====================================================================
__global__ __launch_bounds__(32) void segemit_kernel(float* __restrict__ out)
{
    const int b    = blockIdx.x >> 7;
    const int sg   = blockIdx.x & (NSEG - 1);
    const int lo   = sg * SEGG;
    const int lane = threadIdx.x;

    __shared__ unsigned char bps[SEGG][32];
    __shared__ unsigned char tagbuf[SEGG];
    const unsigned* src = (const unsigned*)(g_bp + (b * LQ + lo) * 32);
    unsigned* dst = (unsigned*)bps;
    for (int i = lane; i < SEGG * 8; i += 32) dst[i] = src[i];
    __syncwarp();

    if (lane == 0) {
        int tag = g_segend[b * NSEG + sg] & 31;
        for (int r = SEGG - 1; r >= 0; r--) {
            tagbuf[r] = (unsigned char)tag;
            if (r > 0) tag = bps[r][tag] & 31;
        }
    }
    __syncwarp();
    for (int i = lane; i < SEGG; i += 32)
        out[b * LQ + lo + i] = (float)tagbuf[i];
}

// =====================================================================
// Host launcher: 2 streams; bp overlaps fwd via progress gating
// =====================================================================
extern "C" void kernel_launch(void* const* d_in, const int* in_sizes, int n_in,
                              void* d_out, int out_size)
{
    const float *x = 0, *w1 = 0, *b1 = 0, *w2 = 0, *tr = 0;
    const float *v21[3] = {0, 0, 0};
    int n21 = 0, xpos = -1;

    int scale = 0;
    for (int i = 0; i < n_in; i++) {
        if (in_sizes[i] == BATCH * 3 * HH * WW)     { scale = 1; break; }
        if (in_sizes[i] == BATCH * 3 * HH * WW * 4) { scale = 4; break; }
    }
    if (scale) {
        for (int i = 0; i < n_in; i++) {
            int sz = in_sizes[i] / scale;
            const float* p = (const float*)d_in[i];
            if      (sz == BATCH * 3 * HH * WW) { x = p; xpos = i; }
            else if (sz == HID * 27)            w1 = p;
            else if (sz == HID)                 b1 = p;
            else if (sz == NC * HID)            w2 = p;
            else if (sz == NC * NC)             tr = p;
            else if (sz == NC && n21 < 3)       v21[n21++] = p;
        }
    }

    const float *b2, *st, *en;
    if (x && w1 && b1 && w2 && tr && n21 == 3) {
        if (xpos == 0) { b2 = v21[0]; st = v21[1]; en = v21[2]; }  // insertion
        else           { b2 = v21[0]; en = v21[1]; st = v21[2]; }  // name-sorted
    } else {
        x  = (const float*)d_in[0];
        w1 = (const float*)d_in[1];
        b1 = (const float*)d_in[2];
        w2 = (const float*)d_in[3];
        b2 = (const float*)d_in[4];
        st = (const float*)d_in[5];
        en = (const float*)d_in[6];
        tr = (const float*)d_in[7];
    }

    static cudaStream_t s2;
    static cudaEvent_t  e1, e2;
    static int inited = 0;
    if (!inited) {
        cudaStreamCreateWithFlags(&s2, cudaStreamNonBlocking);
        cudaEventCreateWithFlags(&e1, cudaEventDisableTiming);
        cudaEventCreateWithFlags(&e2, cudaEventDisableTiming);
        inited = 1;
    }

    cudaMemcpyToSymbolAsync(c_w2, w2, NC * HID * sizeof(float), 0,
                            cudaMemcpyDeviceToDevice, 0);
    cudaMemcpyToSymbolAsync(c_tr, tr, NC * NC * sizeof(float), 0,
                            cudaMemcpyDeviceToDevice, 0);
    cudaMemcpyToSymbolAsync(c_b1, b1, HID * sizeof(float), 0,
                            cudaMemcpyDeviceToDevice, 0);
    cudaMemcpyToSymbolAsync(c_b2, b2, NC * sizeof(float), 0,
                            cudaMemcpyDeviceToDevice, 0);
    cudaMemcpyToSymbolAsync(c_st, st, NC * sizeof(float), 0,
                            cudaMemcpyDeviceToDevice, 0);
    cudaMemcpyToSymbolAsync(c_en, en, NC * sizeof(float), 0,
                            cudaMemcpyDeviceToDevice, 0);

    float* out = (float*)d_out;

    // emissions part 1 (t < T0SPLIT) — resets g_p2done + g_progress
    emis_kernel<<<BATCH * P1BPB, 256, 0, 0>>>(x, w1, 0, P1BPB);
    cudaEventRecord(e1, 0);

    // fwd on side stream (ready first -> gets SMs before bp)
    cudaStreamWaitEvent(s2, e1, 0);
    fwd_kernel<<<BATCH, 32, 0, s2>>>();
    cudaEventRecord(e2, s2);

    // emissions part 2 (t >= T0SPLIT) on main stream
    emis_kernel<<<BATCH * P2BPB, 256, 0, 0>>>(x, w1, T0SPLIT, P2BPB);

    // bp overlaps fwd: gated internally on g_progress
    bp_kernel<<<BATCH * 64, 256, 0, 0>>>();

    // join (fwd certainly done once bp finished, but keep the edge)
    cudaStreamWaitEvent(0, e2, 0);

    segmap_kernel<<<BATCH * NSEG, 32, 0, 0>>>();
    compose_kernel<<<BATCH, 32, 0, 0>>>();
    segemit_kernel<<<BATCH * NSEG, 32, 0, 0>>>(out);
}

// round 15
// speedup vs baseline: 1.2378x; 1.2378x over previous
#include <cuda_runtime.h>
#include <cstdint>

#define BATCH 16
#define LQ    16384
#define NC    21
#define HID   256
#define HH    128
#define WW    128
#define SEGG  128
#define NSEG  128

#define T0SPLIT   4096
#define P1BPB     (T0SPLIT / 256)            // 16 blocks per batch
#define P2BPB     ((LQ - T0SPLIT) / 256)     // 48 blocks per batch
#define P2BLOCKS  (BATCH * P2BPB)            // 768

typedef unsigned long long u64;

// ---------------- constant memory for small params ----------------
__constant__ float c_w2  [NC * HID];
__constant__ float c_tr  [NC * NC];
__constant__ float c_b1  [HID];
__constant__ float c_b2  [NC];
__constant__ float c_st  [NC];
__constant__ float c_en  [NC];

// ---------------- device scratch ----------------
__device__ float         g_emis  [BATCH * LQ * 32];   // row layout (bp)
__device__ float         g_emisT [BATCH * NC * LQ];   // transposed (fwd)
__device__ float         g_scores[BATCH * LQ * 32];
__device__ unsigned char g_bp    [BATCH * LQ * 32];
__device__ unsigned char g_segmap[BATCH * NSEG * 32];
__device__ unsigned char g_segend[BATCH * NSEG];
__device__ int           g_lasttag[BATCH];
__device__ int           g_p2done;

// ---------------- f32x2 helpers ----------------
__device__ __forceinline__ u64 pk2(float lo, float hi)
{ u64 r; asm("mov.b64 %0,{%1,%2};" : "=l"(r) : "f"(lo), "f"(hi)); return r; }
__device__ __forceinline__ void upk2(u64 v, float& lo, float& hi)
{ asm("mov.b64 {%0,%1},%2;" : "=f"(lo), "=f"(hi) : "l"(v)); }
__device__ __forceinline__ u64 fma2(u64 a, u64 b, u64 c)
{ u64 d; asm("fma.rn.f32x2 %0,%1,%2,%3;" : "=l"(d) : "l"(a), "l"(b), "l"(c)); return d; }

// ---------------- ordered smem ops (warp-lockstep comms) ----------------
__device__ __forceinline__ uint32_t smem_u32(const void* p)
{ uint32_t a; asm("{ .reg .u64 t; cvta.to.shared.u64 t, %1; cvt.u32.u64 %0, t; }"
                  : "=r"(a) : "l"(p)); return a; }
__device__ __forceinline__ void sts32(uint32_t addr, float v)
{ asm volatile("st.shared.b32 [%0], %1;" :: "r"(addr), "f"(v)); }
__device__ __forceinline__ float4 lds128(uint32_t addr)
{ float4 r; asm volatile("ld.shared.v4.f32 {%0,%1,%2,%3}, [%4];"
      : "=f"(r.x), "=f"(r.y), "=f"(r.z), "=f"(r.w) : "r"(addr)); return r; }
__device__ __forceinline__ float lds32(uint32_t addr)
{ float r; asm volatile("ld.shared.f32 %0, [%1];" : "=f"(r) : "r"(addr)); return r; }

// =====================================================================
// Kernel 1: fused conv backbone; writes BOTH emission layouts.
// conv1 packed over h-pairs (bit-identical to scalar).
// =====================================================================
__global__ __launch_bounds__(256) void emis_kernel(
    const float* __restrict__ x,
    const float* __restrict__ w1,
    int t0, int bpb)
{
    __shared__ u64 w1p[128 * 28];
    const int tid = threadIdx.x;

    if (t0 == 0 && blockIdx.x == 0 && tid == 0) g_p2done = 0;

    for (int i = tid; i < 128 * 27; i += 256) {
        int h2 = i / 27, k = i - h2 * 27;
        w1p[h2 * 28 + k] = pk2(w1[(2 * h2) * 27 + k], w1[(2 * h2 + 1) * 27 + k]);
    }
    __syncthreads();

    const int b = blockIdx.x / bpb;
    const int t = t0 + (blockIdx.x % bpb) * 256 + tid;
    const int y  = t >> 7;
    const int xx = t & 127;

    float patch[27];
#pragma unroll
    for (int ci = 0; ci < 3; ci++)
#pragma unroll
        for (int dy = 0; dy < 3; dy++)
#pragma unroll
            for (int dx = 0; dx < 3; dx++) {
                int yy = y + dy - 1;
                int xi = xx + dx - 1;
                bool ok = (yy >= 0) & (yy < HH) & (xi >= 0) & (xi < WW);
                patch[ci * 9 + dy * 3 + dx] =
                    ok ? x[((b * 3 + ci) * HH + yy) * WW + xi] : 0.0f;
            }

    u64 pp[27];
#pragma unroll
    for (int k = 0; k < 27; k++) pp[k] = pk2(patch[k], patch[k]);

    float emit[NC];
#pragma unroll
    for (int c = 0; c < NC; c++) emit[c] = 0.0f;

#pragma unroll 2
    for (int h2 = 0; h2 < 128; h2++) {
        u64 a2 = 0;
#pragma unroll
        for (int k = 0; k < 27; k++)
            a2 = fma2(w1p[h2 * 28 + k], pp[k], a2);

        float aE, aO;
        upk2(a2, aE, aO);
        aE = fmaxf(aE + c_b1[2 * h2],     0.0f);
        aO = fmaxf(aO + c_b1[2 * h2 + 1], 0.0f);

#pragma unroll
        for (int c = 0; c < NC; c++)
            emit[c] = __fmaf_rn(c_w2[c * HID + 2 * h2], aE, emit[c]);
#pragma unroll
        for (int c = 0; c < NC; c++)
            emit[c] = __fmaf_rn(c_w2[c * HID + 2 * h2 + 1], aO, emit[c]);
    }

    const int base = (b * LQ + t) * 32;
#pragma unroll
    for (int c = 0; c < NC; c++) {
        float v = emit[c] + c_b2[c];
        g_emis[base + c] = v;
        g_emisT[(b * NC + c) * LQ + t] = v;
    }

    if (t0 > 0) {
        __syncthreads();
        if (tid == 0) { __threadfence(); atomicAdd(&g_p2done, 1); }
    }
}

// =====================================================================
// Kernel 2: Viterbi forward, 1 warp per batch, lockstep smem broadcast
// (per-chunk syncwarp guard). Emission reloads from transposed layout:
// 2x LDG.128 per 8 steps. Values bit-exact vs reference.
// =====================================================================
__device__ __forceinline__ float step_math(
    float4 a, float4 b4, float4 c4, float4 d4, float4 f4, float g,
    float e, const float* Tc)
{
    float v[NC];
    v[0]  = __fmaf_rn(a.x,  1.0f, Tc[0]);
    v[1]  = __fmaf_rn(a.y,  1.0f, Tc[1]);
    v[2]  = __fmaf_rn(a.z,  1.0f, Tc[2]);
    v[3]  = __fmaf_rn(a.w,  1.0f, Tc[3]);
    v[4]  = __fmaf_rn(b4.x, 1.0f, Tc[4]);
    v[5]  = __fmaf_rn(b4.y, 1.0f, Tc[5]);
    v[6]  = __fmaf_rn(b4.z, 1.0f, Tc[6]);
    v[7]  = __fmaf_rn(b4.w, 1.0f, Tc[7]);
    v[8]  = __fmaf_rn(c4.x, 1.0f, Tc[8]);
    v[9]  = __fmaf_rn(c4.y, 1.0f, Tc[9]);
    v[10] = __fmaf_rn(c4.z, 1.0f, Tc[10]);
    v[11] = __fmaf_rn(c4.w, 1.0f, Tc[11]);
    v[12] = __fmaf_rn(d4.x, 1.0f, Tc[12]);
    v[13] = __fmaf_rn(d4.y, 1.0f, Tc[13]);
    v[14] = __fmaf_rn(d4.z, 1.0f, Tc[14]);
    v[15] = __fmaf_rn(d4.w, 1.0f, Tc[15]);
    v[16] = __fmaf_rn(f4.x, 1.0f, Tc[16]);
    v[17] = __fmaf_rn(f4.y, 1.0f, Tc[17]);
    v[18] = __fmaf_rn(f4.z, 1.0f, Tc[18]);
    v[19] = __fmaf_rn(f4.w, 1.0f, Tc[19]);
    v[20] = __fmaf_rn(g,    1.0f, Tc[20]);

#pragma unroll
    for (int st = 1; st < NC; st <<= 1)
#pragma unroll
        for (int i = 0; i + st < NC; i += 2 * st)
            v[i] = fmaxf(v[i], v[i + st]);

    return __fmaf_rn(v[0], 1.0f, e);
}

#define FWD_STEP(RBASE, WLANE, EJ, SOFF)                                 \
    {                                                                    \
        float4 A = lds128(RBASE);                                        \
        float4 B = lds128((RBASE) + 16);                                 \
        float4 C = lds128((RBASE) + 32);                                 \
        float4 D = lds128((RBASE) + 48);                                 \
        float4 F = lds128((RBASE) + 64);                                 \
        float  G = lds32((RBASE) + 80);                                  \
        s = step_math(A, B, C, D, F, G, EJ, Tc);                         \
        sts32(WLANE, s);                                                 \
        Sp[SOFF] = s;                                                    \
    }

#define CHUNK8()                                                         \
    __syncwarp();                                                        \
    FWD_STEP(a1, a0w, ep[0], 0 * 32)                                     \
    FWD_STEP(a0, a1w, ep[1], 1 * 32)                                     \
    FWD_STEP(a1, a0w, ep[2], 2 * 32)                                     \
    FWD_STEP(a0, a1w, ep[3], 3 * 32)                                     \
    FWD_STEP(a1, a0w, ep[4], 4 * 32)                                     \
    FWD_STEP(a0, a1w, ep[5], 5 * 32)                                     \
    FWD_STEP(a1, a0w, ep[6], 6 * 32)                                     \
    FWD_STEP(a0, a1w, ep[7], 7 * 32)

#define RELOAD8()                                                        \
    {                                                                    \
        float4 u0 = __ldg((const float4*)EpT);                           \
        float4 u1 = __ldg((const float4*)(EpT + 4));                     \
        ep[0] = u0.x; ep[1] = u0.y; ep[2] = u0.z; ep[3] = u0.w;          \
        ep[4] = u1.x; ep[5] = u1.y; ep[6] = u1.z; ep[7] = u1.w;          \
        EpT += 8;                                                        \
    }

// chunk counts: steps 8..16383 = 2047 chunks of 8.
//   loop1 = T0SPLIT/8 - 2 = 510   (t: 8 .. 4087; reloads stay < 4096)
//   loop2 = (LQ - T0SPLIT)/8 = 1536 (t: 4088 .. 16375)
//   tail  = 1 chunk, no reload      (t: 16376 .. 16383)
//   check: 510 + 1536 + 1 = 2047  OK
#define L1CHUNKS (T0SPLIT / 8 - 2)
#define L2CHUNKS ((LQ - T0SPLIT) / 8)

__global__ __launch_bounds__(32) void fwd_kernel()
{
    const int b    = blockIdx.x;
    const int lane = threadIdx.x;
    const int nn   = lane < NC ? lane : NC - 1;

    const float* ET = g_emisT  + (b * NC + nn) * LQ;   // lane's emission row
    float*       S  = g_scores + b * LQ * 32;

    __shared__ __align__(16) float sb0[32];
    __shared__ __align__(16) float sb1[32];

    const uint32_t a0  = smem_u32(sb0);
    const uint32_t a1  = smem_u32(sb1);
    const uint32_t a0w = a0 + lane * 4;
    const uint32_t a1w = a1 + lane * 4;

    float Tc[NC];
#pragma unroll
    for (int p = 0; p < NC; p++) Tc[p] = c_tr[p * NC + nn];

    // t = 0 -> sb0 (invariant: after step t, s lives in sb[t&1])
    float s = __fmaf_rn(ET[0], 1.0f, c_st[nn]);
    S[lane] = s;
    sts32(a0w, s);

    // peel t = 1..7
#pragma unroll
    for (int t = 1; t < 8; t++) {
        float e = __ldg(&ET[t]);
        uint32_t rb = (t & 1) ? a0 : a1;
        uint32_t wb = (t & 1) ? a1w : a0w;
        __syncwarp();
        float4 A = lds128(rb);
        float4 B = lds128(rb + 16);
        float4 C = lds128(rb + 32);
        float4 D = lds128(rb + 48);
        float4 F = lds128(rb + 64);
        float  G = lds32(rb + 80);
        s = step_math(A, B, C, D, F, G, e, Tc);
        sts32(wb, s);
        S[t * 32 + lane] = s;
    }

    // prefetch t = 8..15 (vector loads from transposed layout)
    float ep[8];
    {
        float4 u0 = __ldg((const float4*)(ET + 8));
        float4 u1 = __ldg((const float4*)(ET + 12));
        ep[0] = u0.x; ep[1] = u0.y; ep[2] = u0.z; ep[3] = u0.w;
        ep[4] = u1.x; ep[5] = u1.y; ep[6] = u1.z; ep[7] = u1.w;
    }

    float*       Sp  = S + 8 * 32 + lane;
    const float* EpT = ET + 16;

    // loop 1: t = 8 .. 4087
#pragma unroll 1
    for (int c = 0; c < L1CHUNKS; c++) {
        CHUNK8()
        RELOAD8()
        Sp += 256;
    }

    // wait for emis part 2 (t >= T0SPLIT)
    while (*(volatile int*)&g_p2done < P2BLOCKS) { }
    __threadfence();

    // loop 2: t = 4088 .. 16375
#pragma unroll 1
    for (int c = 0; c < L2CHUNKS; c++) {
        CHUNK8()
        RELOAD8()
        Sp += 256;
    }

    // final chunk t = 16376..16383, no reload
    CHUNK8()

    // final tag: first-max over lanes 0..20
    float vend = s + c_en[nn];
    __shared__ float vs[32];
    vs[lane] = vend;
    __syncwarp();
    if (lane == 0) {
        float best = vs[0];
        int   bi   = 0;
#pragma unroll
        for (int p = 1; p < NC; p++)
            if (vs[p] > best) { best = vs[p]; bi = p; }
        g_lasttag[b] = bi;
    }
}

// =====================================================================
// Kernel 3: backpointers, parallel over (b, t>=1).
// =====================================================================
__global__ __launch_bounds__(256) void bp_kernel()
{
    const int gid = blockIdx.x * 256 + threadIdx.x;
    const int b = gid >> 14;
    const int t = gid & (LQ - 1);
    if (t == 0) return;

    const float* Sp = g_scores + (b * LQ + (t - 1)) * 32;
    const float* Ee = g_emis   + (b * LQ + t) * 32;
    unsigned char* bp = g_bp   + (b * LQ + t) * 32;

    float sv[NC], ev[NC];
#pragma unroll
    for (int p = 0; p < NC; p++) sv[p] = Sp[p];
#pragma unroll
    for (int c = 0; c < NC; c++) ev[c] = Ee[c];

#pragma unroll 3
    for (int n = 0; n < NC; n++) {
        float best = -3.0e38f;
        int bi = 0;
        float e = ev[n];
#pragma unroll
        for (int p = 0; p < NC; p++) {
            float a = __fmaf_rn(sv[p], 1.0f, c_tr[p * NC + n]);
            float v = __fmaf_rn(a,     1.0f, e);
            if (v > best) { best = v; bi = p; }
        }
        bp[n] = (unsigned char)bi;
    }
}

// =====================================================================
// Kernel 4a: per-segment end->start tag maps
// =====================================================================
__global__ __launch_bounds__(32) void segmap_kernel()
{
    const int b    = blockIdx.x >> 7;
    const int sg   = blockIdx.x & (NSEG - 1);
    const int lo   = sg * SEGG;
    const int lane = threadIdx.x;

    __shared__ unsigned char bps[SEGG][32];
    const unsigned* src = (const unsigned*)(g_bp + (b * LQ + lo) * 32);
    unsigned* dst = (unsigned*)bps;
    for (int i = lane; i < SEGG * 8; i += 32) dst[i] = src[i];
    __syncwarp();

    int tag = lane < NC ? lane : NC - 1;
    for (int r = SEGG - 1; r >= 1; r--) tag = bps[r][tag & 31];
    g_segmap[(b * NSEG + sg) * 32 + lane] = (unsigned char)tag;
}

// =====================================================================
// Kernel 4b: compose maps -> tag at end of every segment
// =====================================================================
__global__ __launch_bounds__(32) void compose_kernel()
{
    const int b    = blockIdx.x;
    const int lane = threadIdx.x;

    __shared__ unsigned char maps[NSEG][32];
    __shared__ unsigned char bnd [NSEG][32];
    __shared__ unsigned char se  [NSEG];

    {
        const unsigned* src = (const unsigned*)(g_segmap + b * NSEG * 32);
        unsigned* dst = (unsigned*)maps;
        for (int i = lane; i < NSEG * 8; i += 32) dst[i] = src[i];
        unsigned* dstb = (unsigned*)bnd;
        const unsigned* gb = (const unsigned*)g_bp;
        for (int i = lane; i < NSEG * 8; i += 32) {
            int s2 = i >> 3, w = i & 7;
            dstb[i] = gb[(size_t)(b * LQ + s2 * SEGG) * 8 + w];
        }
    }
    __syncwarp();

    if (lane == 0) {
        int tag = g_lasttag[b] & 31;
        for (int s2 = NSEG - 1; s2 >= 0; s2--) {
            se[s2] = (unsigned char)tag;
            int tstart = maps[s2][tag] & 31;
            if (s2 > 0) tag = bnd[s2][tstart] & 31;
        }
    }
    __syncwarp();
    for (int i = lane; i < NSEG; i += 32) g_segend[b * NSEG + i] = se[i];
}

// =====================================================================
// Kernel 4c: re-chase each segment, emit tags as FLOAT
// =====================================================================
__global__ __launch_bounds__(32) void segemit_kernel(float* __restrict__ out)
{
    const int b    = blockIdx.x >> 7;
    const int sg   = blockIdx.x & (NSEG - 1);
    const int lo   = sg * SEGG;
    const int lane = threadIdx.x;

    __shared__ unsigned char bps[SEGG][32];
    __shared__ unsigned char tagbuf[SEGG];
    const unsigned* src = (const unsigned*)(g_bp + (b * LQ + lo) * 32);
    unsigned* dst = (unsigned*)bps;
    for (int i = lane; i < SEGG * 8; i += 32) dst[i] = src[i];
    __syncwarp();

    if (lane == 0) {
        int tag = g_segend[b * NSEG + sg] & 31;
        for (int r = SEGG - 1; r >= 0; r--) {
            tagbuf[r] = (unsigned char)tag;
            if (r > 0) tag = bps[r][tag] & 31;
        }
    }
    __syncwarp();
    for (int i = lane; i < SEGG; i += 32)
        out[b * LQ + lo + i] = (float)tagbuf[i];
}

// =====================================================================
// Host launcher: input resolution + overlapped emis/fwd via 2 streams
// =====================================================================
extern "C" void kernel_launch(void* const* d_in, const int* in_sizes, int n_in,
                              void* d_out, int out_size)
{
    const float *x = 0, *w1 = 0, *b1 = 0, *w2 = 0, *tr = 0;
    const float *v21[3] = {0, 0, 0};
    int n21 = 0, xpos = -1;

    int scale = 0;
    for (int i = 0; i < n_in; i++) {
        if (in_sizes[i] == BATCH * 3 * HH * WW)     { scale = 1; break; }
        if (in_sizes[i] == BATCH * 3 * HH * WW * 4) { scale = 4; break; }
    }
    if (scale) {
        for (int i = 0; i < n_in; i++) {
            int sz = in_sizes[i] / scale;
            const float* p = (const float*)d_in[i];
            if      (sz == BATCH * 3 * HH * WW) { x = p; xpos = i; }
            else if (sz == HID * 27)            w1 = p;
            else if (sz == HID)                 b1 = p;
            else if (sz == NC * HID)            w2 = p;
            else if (sz == NC * NC)             tr = p;
            else if (sz == NC && n21 < 3)       v21[n21++] = p;
        }
    }

    const float *b2, *st, *en;
    if (x && w1 && b1 && w2 && tr && n21 == 3) {
        if (xpos == 0) { b2 = v21[0]; st = v21[1]; en = v21[2]; }  // insertion
        else           { b2 = v21[0]; en = v21[1]; st = v21[2]; }  // name-sorted
    } else {
        x  = (const float*)d_in[0];
        w1 = (const float*)d_in[1];
        b1 = (const float*)d_in[2];
        w2 = (const float*)d_in[3];
        b2 = (const float*)d_in[4];
        st = (const float*)d_in[5];
        en = (const float*)d_in[6];
        tr = (const float*)d_in[7];
    }

    static cudaStream_t s2;
    static cudaEvent_t  e1, e2;
    static int inited = 0;
    if (!inited) {
        cudaStreamCreateWithFlags(&s2, cudaStreamNonBlocking);
        cudaEventCreateWithFlags(&e1, cudaEventDisableTiming);
        cudaEventCreateWithFlags(&e2, cudaEventDisableTiming);
        inited = 1;
    }

    cudaMemcpyToSymbolAsync(c_w2, w2, NC * HID * sizeof(float), 0,
                            cudaMemcpyDeviceToDevice, 0);
    cudaMemcpyToSymbolAsync(c_tr, tr, NC * NC * sizeof(float), 0,
                            cudaMemcpyDeviceToDevice, 0);
    cudaMemcpyToSymbolAsync(c_b1, b1, HID * sizeof(float), 0,
                            cudaMemcpyDeviceToDevice, 0);
    cudaMemcpyToSymbolAsync(c_b2, b2, NC * sizeof(float), 0,
                            cudaMemcpyDeviceToDevice, 0);
    cudaMemcpyToSymbolAsync(c_st, st, NC * sizeof(float), 0,
                            cudaMemcpyDeviceToDevice, 0);
    cudaMemcpyToSymbolAsync(c_en, en, NC * sizeof(float), 0,
                            cudaMemcpyDeviceToDevice, 0);

    float* out = (float*)d_out;

    // emissions part 1 (t < T0SPLIT) — resets g_p2done
    emis_kernel<<<BATCH * P1BPB, 256, 0, 0>>>(x, w1, 0, P1BPB);
    cudaEventRecord(e1, 0);

    // fwd on side stream, concurrent with emis part 2
    cudaStreamWaitEvent(s2, e1, 0);
    fwd_kernel<<<BATCH, 32, 0, s2>>>();
    cudaEventRecord(e2, s2);

    // emissions part 2 (t >= T0SPLIT) on the main stream
    emis_kernel<<<BATCH * P2BPB, 256, 0, 0>>>(x, w1, T0SPLIT, P2BPB);

    // join: everything after needs fwd + emis complete
    cudaStreamWaitEvent(0, e2, 0);

    bp_kernel<<<(BATCH * LQ) / 256, 256, 0, 0>>>();
    segmap_kernel<<<BATCH * NSEG, 32, 0, 0>>>();
    compose_kernel<<<BATCH, 32, 0, 0>>>();
    segemit_kernel<<<BATCH * NSEG, 32, 0, 0>>>(out);
}

// round 17
// speedup vs baseline: 1.2415x; 1.0030x over previous
#include <cuda_runtime.h>
#include <cstdint>

#define BATCH 16
#define LQ    16384
#define NC    21
#define HID   256
#define HH    128
#define WW    128
#define SEGG  128
#define NSEG  128

#define T0SPLIT   4096
#define P1BPB     (T0SPLIT / 256)            // 16 blocks per batch
#define P2BPB     ((LQ - T0SPLIT) / 256)     // 48 blocks per batch
#define P2BLOCKS  (BATCH * P2BPB)            // 768

typedef unsigned long long u64;

// ---------------- constant memory for small params ----------------
__constant__ float c_w2  [NC * HID];
__constant__ float c_tr  [NC * NC];
__constant__ float c_b1  [HID];
__constant__ float c_b2  [NC];
__constant__ float c_st  [NC];
__constant__ float c_en  [NC];

// ---------------- device scratch ----------------
__device__ float         g_emis  [BATCH * LQ * 32];   // row layout (bp)
__device__ float         g_emisT [BATCH * NC * LQ];   // transposed (fwd)
__device__ float         g_scores[BATCH * LQ * 32];
__device__ unsigned char g_bp    [BATCH * LQ * 32];
__device__ unsigned char g_segmap[BATCH * NSEG * 32];
__device__ unsigned char g_segend[BATCH * NSEG];
__device__ int           g_lasttag[BATCH];
__device__ int           g_p2done;

// ---------------- f32x2 helpers ----------------
__device__ __forceinline__ u64 pk2(float lo, float hi)
{ u64 r; asm("mov.b64 %0,{%1,%2};" : "=l"(r) : "f"(lo), "f"(hi)); return r; }
__device__ __forceinline__ void upk2(u64 v, float& lo, float& hi)
{ asm("mov.b64 {%0,%1},%2;" : "=f"(lo), "=f"(hi) : "l"(v)); }
__device__ __forceinline__ u64 fma2(u64 a, u64 b, u64 c)
{ u64 d; asm("fma.rn.f32x2 %0,%1,%2,%3;" : "=l"(d) : "l"(a), "l"(b), "l"(c)); return d; }

// ---------------- ordered smem ops (warp-lockstep comms) ----------------
__device__ __forceinline__ uint32_t smem_u32(const void* p)
{ uint32_t a; asm("{ .reg .u64 t; cvta.to.shared.u64 t, %1; cvt.u32.u64 %0, t; }"
                  : "=r"(a) : "l"(p)); return a; }
__device__ __forceinline__ void sts32(uint32_t addr, float v)
{ asm volatile("st.shared.b32 [%0], %1;" :: "r"(addr), "f"(v)); }
__device__ __forceinline__ float4 lds128(uint32_t addr)
{ float4 r; asm volatile("ld.shared.v4.f32 {%0,%1,%2,%3}, [%4];"
      : "=f"(r.x), "=f"(r.y), "=f"(r.z), "=f"(r.w) : "r"(addr)); return r; }
__device__ __forceinline__ float lds32(uint32_t addr)
{ float r; asm volatile("ld.shared.f32 %0, [%1];" : "=f"(r) : "r"(addr)); return r; }

// =====================================================================
// Kernel 1: fused conv backbone; writes BOTH emission layouts.
// =====================================================================
__global__ __launch_bounds__(256) void emis_kernel(
    const float* __restrict__ x,
    const float* __restrict__ w1,
    int t0, int bpb)
{
    __shared__ u64 w1p[128 * 28];
    const int tid = threadIdx.x;

    if (t0 == 0 && blockIdx.x == 0 && tid == 0) g_p2done = 0;

    for (int i = tid; i < 128 * 27; i += 256) {
        int h2 = i / 27, k = i - h2 * 27;
        w1p[h2 * 28 + k] = pk2(w1[(2 * h2) * 27 + k], w1[(2 * h2 + 1) * 27 + k]);
    }
    __syncthreads();

    const int b = blockIdx.x / bpb;
    const int t = t0 + (blockIdx.x % bpb) * 256 + tid;
    const int y  = t >> 7;
    const int xx = t & 127;

    float patch[27];
#pragma unroll
    for (int ci = 0; ci < 3; ci++)
#pragma unroll
        for (int dy = 0; dy < 3; dy++)
#pragma unroll
            for (int dx = 0; dx < 3; dx++) {
                int yy = y + dy - 1;
                int xi = xx + dx - 1;
                bool ok = (yy >= 0) & (yy < HH) & (xi >= 0) & (xi < WW);
                patch[ci * 9 + dy * 3 + dx] =
                    ok ? x[((b * 3 + ci) * HH + yy) * WW + xi] : 0.0f;
            }

    u64 pp[27];
#pragma unroll
    for (int k = 0; k < 27; k++) pp[k] = pk2(patch[k], patch[k]);

    float emit[NC];
#pragma unroll
    for (int c = 0; c < NC; c++) emit[c] = 0.0f;

#pragma unroll 2
    for (int h2 = 0; h2 < 128; h2++) {
        u64 a2 = 0;
#pragma unroll
        for (int k = 0; k < 27; k++)
            a2 = fma2(w1p[h2 * 28 + k], pp[k], a2);

        float aE, aO;
        upk2(a2, aE, aO);
        aE = fmaxf(aE + c_b1[2 * h2],     0.0f);
        aO = fmaxf(aO + c_b1[2 * h2 + 1], 0.0f);

#pragma unroll
        for (int c = 0; c < NC; c++)
            emit[c] = __fmaf_rn(c_w2[c * HID + 2 * h2], aE, emit[c]);
#pragma unroll
        for (int c = 0; c < NC; c++)
            emit[c] = __fmaf_rn(c_w2[c * HID + 2 * h2 + 1], aO, emit[c]);
    }

    const int base = (b * LQ + t) * 32;
#pragma unroll
    for (int c = 0; c < NC; c++) {
        float v = emit[c] + c_b2[c];
        g_emis[base + c] = v;
        g_emisT[(b * NC + c) * LQ + t] = v;
    }

    if (t0 > 0) {
        __syncthreads();
        if (tid == 0) { __threadfence(); atomicAdd(&g_p2done, 1); }
    }
}

// =====================================================================
// Kernel 2: Viterbi forward, 1 warp per batch, lockstep smem broadcast.
// THIS ROUND: no per-chunk __syncwarp — converged warp + volatile-asm
// STS/LDS ordering provide cross-lane visibility. Emission reloads
// from transposed layout: 2x LDG.128 per 8 steps. Bit-exact values.
// =====================================================================
__device__ __forceinline__ float step_math(
    float4 a, float4 b4, float4 c4, float4 d4, float4 f4, float g,
    float e, const float* Tc)
{
    float v[NC];
    v[0]  = __fmaf_rn(a.x,  1.0f, Tc[0]);
    v[1]  = __fmaf_rn(a.y,  1.0f, Tc[1]);
    v[2]  = __fmaf_rn(a.z,  1.0f, Tc[2]);
    v[3]  = __fmaf_rn(a.w,  1.0f, Tc[3]);
    v[4]  = __fmaf_rn(b4.x, 1.0f, Tc[4]);
    v[5]  = __fmaf_rn(b4.y, 1.0f, Tc[5]);
    v[6]  = __fmaf_rn(b4.z, 1.0f, Tc[6]);
    v[7]  = __fmaf_rn(b4.w, 1.0f, Tc[7]);
    v[8]  = __fmaf_rn(c4.x, 1.0f, Tc[8]);
    v[9]  = __fmaf_rn(c4.y, 1.0f, Tc[9]);
    v[10] = __fmaf_rn(c4.z, 1.0f, Tc[10]);
    v[11] = __fmaf_rn(c4.w, 1.0f, Tc[11]);
    v[12] = __fmaf_rn(d4.x, 1.0f, Tc[12]);
    v[13] = __fmaf_rn(d4.y, 1.0f, Tc[13]);
    v[14] = __fmaf_rn(d4.z, 1.0f, Tc[14]);
    v[15] = __fmaf_rn(d4.w, 1.0f, Tc[15]);
    v[16] = __fmaf_rn(f4.x, 1.0f, Tc[16]);
    v[17] = __fmaf_rn(f4.y, 1.0f, Tc[17]);
    v[18] = __fmaf_rn(f4.z, 1.0f, Tc[18]);
    v[19] = __fmaf_rn(f4.w, 1.0f, Tc[19]);
    v[20] = __fmaf_rn(g,    1.0f, Tc[20]);

#pragma unroll
    for (int st = 1; st < NC; st <<= 1)
#pragma unroll
        for (int i = 0; i + st < NC; i += 2 * st)
            v[i] = fmaxf(v[i], v[i + st]);

    return __fmaf_rn(v[0], 1.0f, e);
}

#define FWD_STEP(RBASE, WLANE, EJ, SOFF)                                 \
    {                                                                    \
        float4 A = lds128(RBASE);                                        \
        float4 B = lds128((RBASE) + 16);                                 \
        float4 C = lds128((RBASE) + 32);                                 \
        float4 D = lds128((RBASE) + 48);                                 \
        float4 F = lds128((RBASE) + 64);                                 \
        float  G = lds32((RBASE) + 80);                                  \
        s = step_math(A, B, C, D, F, G, EJ, Tc);                         \
        sts32(WLANE, s);                                                 \
        Sp[SOFF] = s;                                                    \
    }

#define CHUNK8()                                                         \
    FWD_STEP(a1, a0w, ep[0], 0 * 32)                                     \
    FWD_STEP(a0, a1w, ep[1], 1 * 32)                                     \
    FWD_STEP(a1, a0w, ep[2], 2 * 32)                                     \
    FWD_STEP(a0, a1w, ep[3], 3 * 32)                                     \
    FWD_STEP(a1, a0w, ep[4], 4 * 32)                                     \
    FWD_STEP(a0, a1w, ep[5], 5 * 32)                                     \
    FWD_STEP(a1, a0w, ep[6], 6 * 32)                                     \
    FWD_STEP(a0, a1w, ep[7], 7 * 32)

#define RELOAD8()                                                        \
    {                                                                    \
        float4 u0 = __ldg((const float4*)EpT);                           \
        float4 u1 = __ldg((const float4*)(EpT + 4));                     \
        ep[0] = u0.x; ep[1] = u0.y; ep[2] = u0.z; ep[3] = u0.w;          \
        ep[4] = u1.x; ep[5] = u1.y; ep[6] = u1.z; ep[7] = u1.w;          \
        EpT += 8;                                                        \
    }

// chunk counts: steps 8..16383 = 2047 chunks of 8.
//   loop1 = T0SPLIT/8 - 2 = 510   (t: 8..4087; reloads < 4096)
//   loop2 = (LQ - T0SPLIT)/8 = 1536 (t: 4088..16375)
//   tail  = 1 chunk, no reload      (t: 16376..16383)
//   510 + 1536 + 1 = 2047  OK
#define L1CHUNKS (T0SPLIT / 8 - 2)
#define L2CHUNKS ((LQ - T0SPLIT) / 8)

__global__ __launch_bounds__(32) void fwd_kernel()
{
    const int b    = blockIdx.x;
    const int lane = threadIdx.x;
    const int nn   = lane < NC ? lane : NC - 1;

    const float* ET = g_emisT  + (b * NC + nn) * LQ;
    float*       S  = g_scores + b * LQ * 32;

    __shared__ __align__(16) float sb0[32];
    __shared__ __align__(16) float sb1[32];

    const uint32_t a0  = smem_u32(sb0);
    const uint32_t a1  = smem_u32(sb1);
    const uint32_t a0w = a0 + lane * 4;
    const uint32_t a1w = a1 + lane * 4;

    float Tc[NC];
#pragma unroll
    for (int p = 0; p < NC; p++) Tc[p] = c_tr[p * NC + nn];

    // t = 0 -> sb0 (invariant: after step t, s lives in sb[t&1])
    float s = __fmaf_rn(ET[0], 1.0f, c_st[nn]);
    S[lane] = s;
    sts32(a0w, s);

    // peel t = 1..7 (keeps syncwarp as alignment guard before main loop)
#pragma unroll
    for (int t = 1; t < 8; t++) {
        float e = __ldg(&ET[t]);
        uint32_t rb = (t & 1) ? a0 : a1;
        uint32_t wb = (t & 1) ? a1w : a0w;
        __syncwarp();
        float4 A = lds128(rb);
        float4 B = lds128(rb + 16);
        float4 C = lds128(rb + 32);
        float4 D = lds128(rb + 48);
        float4 F = lds128(rb + 64);
        float  G = lds32(rb + 80);
        s = step_math(A, B, C, D, F, G, e, Tc);
        sts32(wb, s);
        S[t * 32 + lane] = s;
    }

    // prefetch t = 8..15
    float ep[8];
    {
        float4 u0 = __ldg((const float4*)(ET + 8));
        float4 u1 = __ldg((const float4*)(ET + 12));
        ep[0] = u0.x; ep[1] = u0.y; ep[2] = u0.z; ep[3] = u0.w;
        ep[4] = u1.x; ep[5] = u1.y; ep[6] = u1.z; ep[7] = u1.w;
    }

    float*       Sp  = S + 8 * 32 + lane;
    const float* EpT = ET + 16;

    __syncwarp();

    // loop 1: t = 8 .. 4087 (no per-chunk syncwarp)
#pragma unroll 1
    for (int c = 0; c < L1CHUNKS; c++) {
        CHUNK8()
        RELOAD8()
        Sp += 256;
    }

    // wait for emis part 2 (t >= T0SPLIT)
    while (*(volatile int*)&g_p2done < P2BLOCKS) { }
    __threadfence();
    __syncwarp();

    // loop 2: t = 4088 .. 16375
#pragma unroll 1
    for (int c = 0; c < L2CHUNKS; c++) {
        CHUNK8()
        RELOAD8()
        Sp += 256;
    }

    // final chunk t = 16376..16383, no reload
    CHUNK8()

    // final tag: first-max over lanes 0..20
    float vend = s + c_en[nn];
    __shared__ float vs[32];
    vs[lane] = vend;
    __syncwarp();
    if (lane == 0) {
        float best = vs[0];
        int   bi   = 0;
#pragma unroll
        for (int p = 1; p < NC; p++)
            if (vs[p] > best) { best = vs[p]; bi = p; }
        g_lasttag[b] = bi;
    }
}

// =====================================================================
// Kernel 3: backpointers, parallel over (b, t>=1).
// =====================================================================
__global__ __launch_bounds__(256) void bp_kernel()
{
    const int gid = blockIdx.x * 256 + threadIdx.x;
    const int b = gid >> 14;
    const int t = gid & (LQ - 1);
    if (t == 0) return;

    const float* Sp = g_scores + (b * LQ + (t - 1)) * 32;
    const float* Ee = g_emis   + (b * LQ + t) * 32;
    unsigned char* bp = g_bp   + (b * LQ + t) * 32;

    float sv[NC], ev[NC];
#pragma unroll
    for (int p = 0; p < NC; p++) sv[p] = Sp[p];
#pragma unroll
    for (int c = 0; c < NC; c++) ev[c] = Ee[c];

#pragma unroll 3
    for (int n = 0; n < NC; n++) {
        float best = -3.0e38f;
        int bi = 0;
        float e = ev[n];
#pragma unroll
        for (int p = 0; p < NC; p++) {
            float a = __fmaf_rn(sv[p], 1.0f, c_tr[p * NC + n]);
            float v = __fmaf_rn(a,     1.0f, e);
            if (v > best) { best = v; bi = p; }
        }
        bp[n] = (unsigned char)bi;
    }
}

// =====================================================================
// Kernel 4a: per-segment end->start tag maps
// =====================================================================
__global__ __launch_bounds__(32) void segmap_kernel()
{
    const int b    = blockIdx.x >> 7;
    const int sg   = blockIdx.x & (NSEG - 1);
    const int lo   = sg * SEGG;
    const int lane = threadIdx.x;

    __shared__ unsigned char bps[SEGG][32];
    const unsigned* src = (const unsigned*)(g_bp + (b * LQ + lo) * 32);
    unsigned* dst = (unsigned*)bps;
    for (int i = lane; i < SEGG * 8; i += 32) dst[i] = src[i];
    __syncwarp();

    int tag = lane < NC ? lane : NC - 1;
    for (int r = SEGG - 1; r >= 1; r--) tag = bps[r][tag & 31];
    g_segmap[(b * NSEG + sg) * 32 + lane] = (unsigned char)tag;
}

// =====================================================================
// Kernel 4b: compose maps -> tag at end of every segment
// =====================================================================
__global__ __launch_bounds__(32) void compose_kernel()
{
    const int b    = blockIdx.x;
    const int lane = threadIdx.x;

    __shared__ unsigned char maps[NSEG][32];
    __shared__ unsigned char bnd [NSEG][32];
    __shared__ unsigned char se  [NSEG];

    {
        const unsigned* src = (const unsigned*)(g_segmap + b * NSEG * 32);
        unsigned* dst = (unsigned*)maps;
        for (int i = lane; i < NSEG * 8; i += 32) dst[i] = src[i];
        unsigned* dstb = (unsigned*)bnd;
        const unsigned* gb = (const unsigned*)g_bp;
        for (int i = lane; i < NSEG * 8; i += 32) {
            int s2 = i >> 3, w = i & 7;
            dstb[i] = gb[(size_t)(b * LQ + s2 * SEGG) * 8 + w];
        }
    }
    __syncwarp();

    if (lane == 0) {
        int tag = g_lasttag[b] & 31;
        for (int s2 = NSEG - 1; s2 >= 0; s2--) {
            se[s2] = (unsigned char)tag;
            int tstart = maps[s2][tag] & 31;
            if (s2 > 0) tag = bnd[s2][tstart] & 31;
        }
    }
    __syncwarp();
    for (int i = lane; i < NSEG; i += 32) g_segend[b * NSEG + i] = se[i];
}

// =====================================================================
// Kernel 4c: re-chase each segment, emit tags as FLOAT
// =====================================================================
__global__ __launch_bounds__(32) void segemit_kernel(float* __restrict__ out)
{
    const int b    = blockIdx.x >> 7;
    const int sg   = blockIdx.x & (NSEG - 1);
    const int lo   = sg * SEGG;
    const int lane = threadIdx.x;

    __shared__ unsigned char bps[SEGG][32];
    __shared__ unsigned char tagbuf[SEGG];
    const unsigned* src = (const unsigned*)(g_bp + (b * LQ + lo) * 32);
    unsigned* dst = (unsigned*)bps;
    for (int i = lane; i < SEGG * 8; i += 32) dst[i] = src[i];
    __syncwarp();

    if (lane == 0) {
        int tag = g_segend[b * NSEG + sg] & 31;
        for (int r = SEGG - 1; r >= 0; r--) {
            tagbuf[r] = (unsigned char)tag;
            if (r > 0) tag = bps[r][tag] & 31;
        }
    }
    __syncwarp();
    for (int i = lane; i < SEGG; i += 32)
        out[b * LQ + lo + i] = (float)tagbuf[i];
}

// =====================================================================
// Host launcher: R15 topology (2 streams, 1 spinner)
// =====================================================================
extern "C" void kernel_launch(void* const* d_in, const int* in_sizes, int n_in,
                              void* d_out, int out_size)
{
    const float *x = 0, *w1 = 0, *b1 = 0, *w2 = 0, *tr = 0;
    const float *v21[3] = {0, 0, 0};
    int n21 = 0, xpos = -1;

    int scale = 0;
    for (int i = 0; i < n_in; i++) {
        if (in_sizes[i] == BATCH * 3 * HH * WW)     { scale = 1; break; }
        if (in_sizes[i] == BATCH * 3 * HH * WW * 4) { scale = 4; break; }
    }
    if (scale) {
        for (int i = 0; i < n_in; i++) {
            int sz = in_sizes[i] / scale;
            const float* p = (const float*)d_in[i];
            if      (sz == BATCH * 3 * HH * WW) { x = p; xpos = i; }
            else if (sz == HID * 27)            w1 = p;
            else if (sz == HID)                 b1 = p;
            else if (sz == NC * HID)            w2 = p;
            else if (sz == NC * NC)             tr = p;
            else if (sz == NC && n21 < 3)       v21[n21++] = p;
        }
    }

    const float *b2, *st, *en;
    if (x && w1 && b1 && w2 && tr && n21 == 3) {
        if (xpos == 0) { b2 = v21[0]; st = v21[1]; en = v21[2]; }  // insertion
        else           { b2 = v21[0]; en = v21[1]; st = v21[2]; }  // name-sorted
    } else {
        x  = (const float*)d_in[0];
        w1 = (const float*)d_in[1];
        b1 = (const float*)d_in[2];
        w2 = (const float*)d_in[3];
        b2 = (const float*)d_in[4];
        st = (const float*)d_in[5];
        en = (const float*)d_in[6];
        tr = (const float*)d_in[7];
    }

    static cudaStream_t s2;
    static cudaEvent_t  e1, e2;
    static int inited = 0;
    if (!inited) {
        cudaStreamCreateWithFlags(&s2, cudaStreamNonBlocking);
        cudaEventCreateWithFlags(&e1, cudaEventDisableTiming);
        cudaEventCreateWithFlags(&e2, cudaEventDisableTiming);
        inited = 1;
    }

    cudaMemcpyToSymbolAsync(c_w2, w2, NC * HID * sizeof(float), 0,
                            cudaMemcpyDeviceToDevice, 0);
    cudaMemcpyToSymbolAsync(c_tr, tr, NC * NC * sizeof(float), 0,
                            cudaMemcpyDeviceToDevice, 0);
    cudaMemcpyToSymbolAsync(c_b1, b1, HID * sizeof(float), 0,
                            cudaMemcpyDeviceToDevice, 0);
    cudaMemcpyToSymbolAsync(c_b2, b2, NC * sizeof(float), 0,
                            cudaMemcpyDeviceToDevice, 0);
    cudaMemcpyToSymbolAsync(c_st, st, NC * sizeof(float), 0,
                            cudaMemcpyDeviceToDevice, 0);
    cudaMemcpyToSymbolAsync(c_en, en, NC * sizeof(float), 0,
                            cudaMemcpyDeviceToDevice, 0);

    float* out = (float*)d_out;

    // emissions part 1 (t < T0SPLIT) — resets g_p2done
    emis_kernel<<<BATCH * P1BPB, 256, 0, 0>>>(x, w1, 0, P1BPB);
    cudaEventRecord(e1, 0);

    // fwd on side stream, concurrent with emis part 2
    cudaStreamWaitEvent(s2, e1, 0);
    fwd_kernel<<<BATCH, 32, 0, s2>>>();
    cudaEventRecord(e2, s2);

    // emissions part 2 (t >= T0SPLIT) on the main stream
    emis_kernel<<<BATCH * P2BPB, 256, 0, 0>>>(x, w1, T0SPLIT, P2BPB);

    // join: everything after needs fwd + emis complete
    cudaStreamWaitEvent(0, e2, 0);

    bp_kernel<<<(BATCH * LQ) / 256, 256, 0, 0>>>();
    segmap_kernel<<<BATCH * NSEG, 32, 0, 0>>>();
    compose_kernel<<<BATCH, 32, 0, 0>>>();
    segemit_kernel<<<BATCH * NSEG, 32, 0, 0>>>(out);
}